// round 3
// baseline (speedup 1.0000x reference)
#include <cuda_runtime.h>
#include <math.h>

#define NN 50000
#define NE 800000
#define DIN 128
#define HID 192

// ---- scratch (device globals; allocation APIs are forbidden) ----
__device__ float g_h[NN * HID];      // node features
__device__ float g_m[NN * HID];      // transformed features / head p buffer
__device__ float g_p2[NN * 96];      // pos-head intermediate
__device__ float g_r[NN * 96];       // radius-head intermediate
__device__ float g_dinv[NN];         // 1/sqrt(deg) (deg includes self-loop)
__device__ int   g_degi[NN];         // in-degree (edges only)
__device__ int   g_cur[NN];          // CSR fill cursors
__device__ int   g_off[NN + 1];      // CSR row offsets
__device__ int   g_csr_src[NE];      // CSR: source node per edge
__device__ float g_csr_w[NE];        // CSR: dinv[src]*dinv[dst] per edge

// ---------------------------------------------------------------------------
// Degree / CSR construction (all global refs are device-side: safe)
// ---------------------------------------------------------------------------
__global__ void zero_counts_kernel() {
    int i = blockIdx.x * blockDim.x + threadIdx.x;
    if (i < NN) { g_degi[i] = 0; g_cur[i] = 0; }
}

__global__ void deg_count_kernel(const int* __restrict__ dst) {
    int e = blockIdx.x * blockDim.x + threadIdx.x;
    if (e < NE) atomicAdd(&g_degi[dst[e]], 1);
}

// single-block chunked exclusive scan of g_degi -> g_off (50k elements)
__global__ void scan_kernel() {
    __shared__ int s[1024];
    __shared__ int carry_s;
    int tid = threadIdx.x;
    if (tid == 0) carry_s = 0;
    __syncthreads();
    for (int base = 0; base < NN; base += 1024) {
        int i = base + tid;
        int v = (i < NN) ? g_degi[i] : 0;
        s[tid] = v;
        __syncthreads();
        #pragma unroll
        for (int off = 1; off < 1024; off <<= 1) {
            int t = (tid >= off) ? s[tid - off] : 0;
            __syncthreads();
            s[tid] += t;
            __syncthreads();
        }
        int carry = carry_s;
        if (i < NN) g_off[i] = carry + s[tid] - v;   // exclusive
        __syncthreads();
        if (tid == 1023) carry_s += s[1023];
        __syncthreads();
    }
    if (tid == 0) g_off[NN] = carry_s;
}

__global__ void dinv_kernel() {
    int i = blockIdx.x * blockDim.x + threadIdx.x;
    if (i < NN) g_dinv[i] = rsqrtf((float)(g_degi[i] + 1));  // +1 self-loop
}

__global__ void csr_fill_kernel(const int* __restrict__ src, const int* __restrict__ dst) {
    int e = blockIdx.x * blockDim.x + threadIdx.x;
    if (e >= NE) return;
    int s = src[e], d = dst[e];
    int pos = g_off[d] + atomicAdd(&g_cur[d], 1);
    g_csr_src[pos] = s;
    g_csr_w[pos] = g_dinv[s] * g_dinv[d];
}

// ---------------------------------------------------------------------------
// Tiled fp32 GEMM: C[M,N] = A[M,K] @ B[K,N] (+bias) (+relu)
// BM=64, BN=64, BK=16, 256 threads, 4x4 per thread. K multiple of 16.
// A, B, C are proper DEVICE pointers (resolved via cudaGetSymbolAddress).
// ---------------------------------------------------------------------------
__global__ __launch_bounds__(256) void gemm_bias_kernel(
    const float* __restrict__ A, const float* __restrict__ B,
    const float* __restrict__ bias, float* __restrict__ C,
    int M, int N, int K, int relu)
{
    const int BM = 64, BN = 64, BK = 16;
    __shared__ float As[BK][BM + 1];
    __shared__ float Bs[BK][BN];

    int tx = threadIdx.x & 15;
    int ty = threadIdx.x >> 4;
    int row0 = blockIdx.y * BM;
    int col0 = blockIdx.x * BN;

    float acc[4][4] = {};

    for (int k0 = 0; k0 < K; k0 += BK) {
        for (int i = threadIdx.x; i < BM * BK; i += 256) {
            int r = i >> 4, c = i & 15;
            int gr = row0 + r;
            As[c][r] = (gr < M) ? A[(size_t)gr * K + (k0 + c)] : 0.0f;
        }
        for (int i = threadIdx.x; i < BK * BN; i += 256) {
            int r = i >> 6, c = i & 63;
            int gc = col0 + c;
            Bs[r][c] = (gc < N) ? B[(size_t)(k0 + r) * N + gc] : 0.0f;
        }
        __syncthreads();

        #pragma unroll
        for (int kk = 0; kk < BK; kk++) {
            float a[4], b[4];
            #pragma unroll
            for (int i = 0; i < 4; i++) a[i] = As[kk][ty * 4 + i];
            #pragma unroll
            for (int j = 0; j < 4; j++) b[j] = Bs[kk][tx * 4 + j];
            #pragma unroll
            for (int i = 0; i < 4; i++)
                #pragma unroll
                for (int j = 0; j < 4; j++)
                    acc[i][j] = fmaf(a[i], b[j], acc[i][j]);
        }
        __syncthreads();
    }

    #pragma unroll
    for (int i = 0; i < 4; i++) {
        int gr = row0 + ty * 4 + i;
        if (gr >= M) continue;
        #pragma unroll
        for (int j = 0; j < 4; j++) {
            int gc = col0 + tx * 4 + j;
            if (gc >= N) continue;
            float v = acc[i][j];
            if (bias) v += bias[gc];
            if (relu) v = fmaxf(v, 0.0f);
            C[(size_t)gr * N + gc] = v;
        }
    }
}

// ---------------------------------------------------------------------------
// Fused GCN aggregation (deterministic gather, no float atomics):
//   h[n] += relu( dinv[n]^2*m[n] + sum_{e:dst=n} w_e * m[src_e] + convB )
// 16 threads per node; lane owns float4 columns {lane, lane+16, lane+32}.
// All global refs are device-side: safe.
// ---------------------------------------------------------------------------
__device__ __forceinline__ void f4_fma(float4& a, float w, const float4 v) {
    a.x = fmaf(w, v.x, a.x); a.y = fmaf(w, v.y, a.y);
    a.z = fmaf(w, v.z, a.z); a.w = fmaf(w, v.w, a.w);
}

__global__ __launch_bounds__(256) void gcn_agg_kernel(const float* __restrict__ convB) {
    int t = blockIdx.x * blockDim.x + threadIdx.x;
    int node = t >> 4;
    int lane = t & 15;
    if (node >= NN) return;

    float di = g_dinv[node];
    float w0 = di * di;
    const float4* mrow = (const float4*)(g_m + (size_t)node * HID);
    float4 a0 = mrow[lane], a1 = mrow[lane + 16], a2 = mrow[lane + 32];
    a0.x *= w0; a0.y *= w0; a0.z *= w0; a0.w *= w0;
    a1.x *= w0; a1.y *= w0; a1.z *= w0; a1.w *= w0;
    a2.x *= w0; a2.y *= w0; a2.z *= w0; a2.w *= w0;

    int beg = g_off[node], end = g_off[node + 1];
    for (int j = beg; j < end; j++) {
        int s = g_csr_src[j];
        float w = g_csr_w[j];
        const float4* ms = (const float4*)(g_m + (size_t)s * HID);
        f4_fma(a0, w, ms[lane]);
        f4_fma(a1, w, ms[lane + 16]);
        f4_fma(a2, w, ms[lane + 32]);
    }

    const float4* b4 = (const float4*)convB;
    float4 b0 = b4[lane], b1 = b4[lane + 16], b2 = b4[lane + 32];
    float4* hrow = (float4*)(g_h + (size_t)node * HID);
    float4 h0 = hrow[lane], h1 = hrow[lane + 16], h2 = hrow[lane + 32];
    h0.x += fmaxf(a0.x + b0.x, 0.f); h0.y += fmaxf(a0.y + b0.y, 0.f);
    h0.z += fmaxf(a0.z + b0.z, 0.f); h0.w += fmaxf(a0.w + b0.w, 0.f);
    h1.x += fmaxf(a1.x + b1.x, 0.f); h1.y += fmaxf(a1.y + b1.y, 0.f);
    h1.z += fmaxf(a1.z + b1.z, 0.f); h1.w += fmaxf(a1.w + b1.w, 0.f);
    h2.x += fmaxf(a2.x + b2.x, 0.f); h2.y += fmaxf(a2.y + b2.y, 0.f);
    h2.z += fmaxf(a2.z + b2.z, 0.f); h2.w += fmaxf(a2.w + b2.w, 0.f);
    hrow[lane] = h0; hrow[lane + 16] = h1; hrow[lane + 32] = h2;
}

// ---------------------------------------------------------------------------
// Final head: pos = p2 @ Wp3 + bp3 (96->2); radius = sigmoid(r @ Wr2 + br2);
// coords = pos / (|pos| + 1e-8) * radius.  One warp per node.
// ---------------------------------------------------------------------------
__global__ void head_final_kernel(
    const float* __restrict__ Wp3, const float* __restrict__ bp3,
    const float* __restrict__ Wr2, const float* __restrict__ br2,
    float* __restrict__ out)
{
    int w = (blockIdx.x * blockDim.x + threadIdx.x) >> 5;
    int lane = threadIdx.x & 31;
    if (w >= NN) return;
    const float* p2 = g_p2 + (size_t)w * 96;
    const float* rr = g_r + (size_t)w * 96;
    float a0 = 0.0f, a1 = 0.0f, ar = 0.0f;
    #pragma unroll
    for (int i = lane; i < 96; i += 32) {
        float v = p2[i];
        a0 = fmaf(v, Wp3[i * 2 + 0], a0);
        a1 = fmaf(v, Wp3[i * 2 + 1], a1);
        ar = fmaf(rr[i], Wr2[i], ar);
    }
    #pragma unroll
    for (int o = 16; o; o >>= 1) {
        a0 += __shfl_down_sync(0xFFFFFFFFu, a0, o);
        a1 += __shfl_down_sync(0xFFFFFFFFu, a1, o);
        ar += __shfl_down_sync(0xFFFFFFFFu, ar, o);
    }
    if (lane == 0) {
        float p0 = a0 + bp3[0];
        float p1 = a1 + bp3[1];
        float rad = 1.0f / (1.0f + expf(-(ar + br2[0])));
        float nrm = sqrtf(p0 * p0 + p1 * p1) + 1e-8f;
        float scale = rad / nrm;
        out[w * 2 + 0] = p0 * scale;
        out[w * 2 + 1] = p1 * scale;
    }
}

// ---------------------------------------------------------------------------
extern "C" void kernel_launch(void* const* d_in, const int* in_sizes, int n_in,
                              void* d_out, int out_size)
{
    const float *x, *Wp, *bp, *convW, *convB, *Wp1, *bp1, *Wp2, *bp2, *Wp3, *bp3;
    const float *Wr1, *br1, *Wr2, *br2;
    const int *ei;

    if (in_sizes[0] == NN * DIN) {
        // dict order: x, edge_index, Wp, bp, convW, convB, Wp1, bp1, Wp2, bp2,
        //             Wp3, bp3, Wr1, br1, Wr2, br2
        x     = (const float*)d_in[0];
        ei    = (const int*)  d_in[1];
        Wp    = (const float*)d_in[2];  bp    = (const float*)d_in[3];
        convW = (const float*)d_in[4];  convB = (const float*)d_in[5];
        Wp1   = (const float*)d_in[6];  bp1   = (const float*)d_in[7];
        Wp2   = (const float*)d_in[8];  bp2   = (const float*)d_in[9];
        Wp3   = (const float*)d_in[10]; bp3   = (const float*)d_in[11];
        Wr1   = (const float*)d_in[12]; br1   = (const float*)d_in[13];
        Wr2   = (const float*)d_in[14]; br2   = (const float*)d_in[15];
    } else {
        // alphabetical (ASCII) order: Wp, Wp1, Wp2, Wp3, Wr1, Wr2, bp, bp1,
        //   bp2, bp3, br1, br2, convB, convW, edge_index, x
        Wp    = (const float*)d_in[0];
        Wp1   = (const float*)d_in[1];
        Wp2   = (const float*)d_in[2];
        Wp3   = (const float*)d_in[3];
        Wr1   = (const float*)d_in[4];
        Wr2   = (const float*)d_in[5];
        bp    = (const float*)d_in[6];
        bp1   = (const float*)d_in[7];
        bp2   = (const float*)d_in[8];
        bp3   = (const float*)d_in[9];
        br1   = (const float*)d_in[10];
        br2   = (const float*)d_in[11];
        convB = (const float*)d_in[12];
        convW = (const float*)d_in[13];
        ei    = (const int*)  d_in[14];
        x     = (const float*)d_in[15];
    }
    float* out = (float*)d_out;

    // CRITICAL: resolve device-global scratch to real DEVICE pointers.
    // A bare `g_h` in host code is the host-side shadow symbol — on GB300
    // (ATS-coherent) kernels silently write host memory through it.
    float *p_h, *p_m, *p_p2, *p_r;
    cudaGetSymbolAddress((void**)&p_h,  g_h);
    cudaGetSymbolAddress((void**)&p_m,  g_m);
    cudaGetSymbolAddress((void**)&p_p2, g_p2);
    cudaGetSymbolAddress((void**)&p_r,  g_r);

    const int* src = ei;
    const int* dst = ei + NE;

    // CSR build
    zero_counts_kernel<<<(NN + 255) / 256, 256>>>();
    deg_count_kernel<<<(NE + 255) / 256, 256>>>(dst);
    scan_kernel<<<1, 1024>>>();
    dinv_kernel<<<(NN + 255) / 256, 256>>>();
    csr_fill_kernel<<<(NE + 255) / 256, 256>>>(src, dst);

    dim3 g192(3, (NN + 63) / 64);
    dim3 g96(2, (NN + 63) / 64);

    // input projection: h = x @ Wp + bp
    gemm_bias_kernel<<<g192, 256>>>(x, Wp, bp, p_h, NN, HID, DIN, 0);

    // 4 GCN layers
    for (int l = 0; l < 4; l++) {
        gemm_bias_kernel<<<g192, 256>>>(p_h, convW + (size_t)l * HID * HID,
                                        nullptr, p_m, NN, HID, HID, 0);
        gcn_agg_kernel<<<(NN * 16 + 255) / 256, 256>>>(convB + (size_t)l * HID);
    }

    // heads
    gemm_bias_kernel<<<g192, 256>>>(p_h, Wp1, bp1, p_m, NN, HID, HID, 1);
    gemm_bias_kernel<<<g96, 256>>>(p_m, Wp2, bp2, p_p2, NN, 96, HID, 1);
    gemm_bias_kernel<<<g96, 256>>>(p_h, Wr1, br1, p_r, NN, 96, HID, 1);
    head_final_kernel<<<(NN * 32 + 255) / 256, 256>>>(Wp3, bp3, Wr2, br2, out);
}